// round 2
// baseline (speedup 1.0000x reference)
#include <cuda_runtime.h>
#include <math.h>

#define LSEQ   4096
#define NFFT   8192
#define DMODEL 1024
#define ORDER  64
#define EMB    5

// ---- scratch (static device globals: allowed) ----
__device__ float  g_h3[LSEQ * ORDER];        // 1 MB
__device__ float  g_k [DMODEL * LSEQ];       // 16 MB
__device__ float  g_decayA[DMODEL * 64];
__device__ float  g_decayB[DMODEL * 64];
__device__ float2 g_tw[2048];                // quarter twiddle table

// =====================================================================
// Kernel 1: implicit-filter MLP -> h3[l][o], plus decay + twiddle tables
// grid 1024, block 256 (4 rows x 64 features)
// =====================================================================
__global__ __launch_bounds__(256) void k_filter_mlp(
    const float* __restrict__ z, const float* __restrict__ deltas,
    const float* __restrict__ W1, const float* __restrict__ b1,
    const float* __restrict__ freq, const float* __restrict__ W2,
    const float* __restrict__ b2, const float* __restrict__ W3,
    const float* __restrict__ b3)
{
    __shared__ float sW1[ORDER * EMB], sb1[ORDER];
    __shared__ float sW2[ORDER * ORDER], sb2[ORDER];
    __shared__ float sW3[ORDER * ORDER], sb3[ORDER];
    __shared__ float sfreq[ORDER];
    __shared__ float h1[4][ORDER], h2[4][ORDER];

    int tid = threadIdx.x;
    for (int i = tid; i < ORDER * EMB; i += 256) sW1[i] = W1[i];
    for (int i = tid; i < ORDER * ORDER; i += 256) { sW2[i] = W2[i]; sW3[i] = W3[i]; }
    if (tid < ORDER) { sb1[tid] = b1[tid]; sb2[tid] = b2[tid]; sb3[tid] = b3[tid]; sfreq[tid] = freq[tid]; }
    __syncthreads();

    int r = tid >> 6;       // 0..3
    int o = tid & 63;       // 0..63
    int l = blockIdx.x * 4 + r;

    // layer 1: h1[o] = sin(freq[o]*(sum_e z[l][e]*W1[o][e] + b1[o]))
    float acc = sb1[o];
#pragma unroll
    for (int e = 0; e < EMB; e++) acc += z[l * EMB + e] * sW1[o * EMB + e];
    h1[r][o] = sinf(sfreq[o] * acc);
    __syncthreads();

    // layer 2: h2[p] = sin(freq[p]*(sum_o h1[o]*W2[p][o] + b2[p]))
    acc = sb2[o];
#pragma unroll
    for (int j = 0; j < ORDER; j++) acc += h1[r][j] * sW2[o * ORDER + j];
    h2[r][o] = sinf(sfreq[o] * acc);
    __syncthreads();

    // layer 3
    acc = sb3[o];
#pragma unroll
    for (int j = 0; j < ORDER; j++) acc += h2[r][j] * sW3[o * ORDER + j];
    g_h3[l * ORDER + o] = sinf(sfreq[o] * acc);

    // decay factorization tables: decay(d,l) = A[d][l>>6] * B[d][l&63]
    int g = blockIdx.x * 256 + tid;
    if (g < DMODEL * 64) {
        int d = g >> 6, i = g & 63;
        float a = fabsf(deltas[d]);
        g_decayA[g] = __expf(-a * (64.0f * (float)i) * (1.0f / 4095.0f));
        g_decayB[g] = __expf(-a * (float)i * (1.0f / 4095.0f));
    }
    // master twiddle table: w[j] = exp(-2*pi*i*j/8192), j < 2048
    if (g < 2048) {
        float ang = -2.0f * 3.14159265358979323846f * (float)g * (1.0f / 8192.0f);
        float s, c;
        sincosf(ang, &s, &c);
        g_tw[g] = make_float2(c, s);
    }
}

// =====================================================================
// Kernel 2: k[d][l] = (h3[l][:] . W4[d][:]) * decay(d,l)
// 64x64 tiled GEMM; grid (64 l-tiles, 16 d-tiles), block 256 (16x16, 4x4 each)
// =====================================================================
__global__ __launch_bounds__(256) void k_filter_gemm(const float* __restrict__ W4)
{
    __shared__ float sh[64][65];   // h3 tile [l][o]
    __shared__ float sw[64][65];   // W4 tile [d][o]
    int lt = blockIdx.x, dt = blockIdx.y;
    int tid = threadIdx.x;

    for (int i = tid; i < 64 * 64; i += 256) {
        int row = i >> 6, col = i & 63;
        sh[row][col] = g_h3[(lt * 64 + row) * 64 + col];
        sw[row][col] = W4[(dt * 64 + row) * 64 + col];
    }
    __syncthreads();

    int tx = tid & 15, ty = tid >> 4;
    float acc[4][4];
#pragma unroll
    for (int r = 0; r < 4; r++)
#pragma unroll
        for (int c = 0; c < 4; c++) acc[r][c] = 0.0f;

#pragma unroll 8
    for (int o = 0; o < 64; o++) {
        float a[4], b[4];
#pragma unroll
        for (int r = 0; r < 4; r++) a[r] = sh[tx + 16 * r][o];
#pragma unroll
        for (int c = 0; c < 4; c++) b[c] = sw[ty + 16 * c][o];
#pragma unroll
        for (int r = 0; r < 4; r++)
#pragma unroll
            for (int c = 0; c < 4; c++) acc[r][c] += a[r] * b[c];
    }

#pragma unroll
    for (int c = 0; c < 4; c++) {
        int d = dt * 64 + ty + 16 * c;
        float dA = g_decayA[d * 64 + lt];
#pragma unroll
        for (int r = 0; r < 4; r++) {
            int li = tx + 16 * r;
            g_k[(size_t)d * LSEQ + lt * 64 + li] = acc[r][c] * dA * g_decayB[d * 64 + li];
        }
    }
}

// =====================================================================
// Kernel 3: per-channel FFT convolution (5 x 8192-pt FFTs per CTA)
// =====================================================================
__device__ __forceinline__ float2 cmul(float2 a, float2 b) {
    return make_float2(a.x * b.x - a.y * b.y, a.x * b.y + a.y * b.x);
}
// master^e, e in [0, 6144): quarter table + quadrant rotation (no MUFU)
__device__ __forceinline__ float2 twget(const float2* __restrict__ tw, int e) {
    int j = e & 2047;
    int k = e >> 11;
    float2 c = tw[j];
    if (k == 1)      c = make_float2(c.y, -c.x);    // * (-i)
    else if (k == 2) c = make_float2(-c.x, -c.y);   // * (-1)
    return c;
}

template <int SLOG>
__device__ __forceinline__ void r4stage(const float2* __restrict__ src, float2* __restrict__ dst,
                                        const float2* __restrict__ tw, int tid)
{
#pragma unroll
    for (int it = 0; it < 4; it++) {
        int idx = tid + it * 512;              // 0..2047, == q + s*p
        int q = idx & ((1 << SLOG) - 1);
        int p = idx >> SLOG;
        float2 a0 = src[idx];
        float2 a1 = src[idx + 2048];
        float2 a2 = src[idx + 4096];
        float2 a3 = src[idx + 6144];
        float2 t0 = make_float2(a0.x + a2.x, a0.y + a2.y);
        float2 t1 = make_float2(a0.x - a2.x, a0.y - a2.y);
        float2 t2 = make_float2(a1.x + a3.x, a1.y + a3.y);
        float2 t3 = make_float2(a1.x - a3.x, a1.y - a3.y);
        float2 b0 = make_float2(t0.x + t2.x, t0.y + t2.y);
        float2 b2 = make_float2(t0.x - t2.x, t0.y - t2.y);
        float2 b1 = make_float2(t1.x + t3.y, t1.y - t3.x);   // t1 - i*t3
        float2 b3 = make_float2(t1.x - t3.y, t1.y + t3.x);   // t1 + i*t3
        int e1 = p << SLOG;
        float2 w1 = twget(tw, e1);
        float2 w2 = twget(tw, e1 * 2);
        float2 w3 = twget(tw, e1 * 3);
        int ob = q + (p << (SLOG + 2));        // q + s*4p
        dst[ob]                 = b0;
        dst[ob + (1 << SLOG)]   = cmul(b1, w1);
        dst[ob + (2 << SLOG)]   = cmul(b2, w2);
        dst[ob + (3 << SLOG)]   = cmul(b3, w3);
    }
    __syncthreads();
}

__device__ __forceinline__ void r2stage(const float2* __restrict__ src, float2* __restrict__ dst, int tid)
{
#pragma unroll
    for (int it = 0; it < 8; it++) {
        int idx = tid + it * 512;              // 0..4095
        float2 a = src[idx], b = src[idx + 4096];
        dst[idx]        = make_float2(a.x + b.x, a.y + b.y);
        dst[idx + 4096] = make_float2(a.x - b.x, a.y - b.y);
    }
    __syncthreads();
}

// Stockham DIF, natural-order output. Result always ends in B.
__device__ __forceinline__ void fft8192(float2* A, float2* B, const float2* tw, int tid)
{
    r4stage<0>(A, B, tw, tid);
    r4stage<2>(B, A, tw, tid);
    r4stage<4>(A, B, tw, tid);
    r4stage<6>(B, A, tw, tid);
    r4stage<8>(A, B, tw, tid);
    r4stage<10>(B, A, tw, tid);
    r2stage(A, B, tid);
}

__global__ __launch_bounds__(512) void k_conv(const float* __restrict__ x,
                                              const float* __restrict__ bias,
                                              float* __restrict__ out)
{
    extern __shared__ float2 sm[];
    float2* bufA = sm;
    float2* bufB = sm + 8192;
    float2* bufK = sm + 16384;
    float2* twS  = sm + 24576;   // 2048 entries

    int tid = threadIdx.x;
    int d = blockIdx.x;

    for (int i = tid; i < 2048; i += 512) twS[i] = g_tw[i];
    for (int i = tid; i < 4096; i += 512) bufA[i] = make_float2(g_k[(size_t)d * LSEQ + i], 0.0f);
    for (int i = tid; i < 4096; i += 512) bufA[4096 + i] = make_float2(0.0f, 0.0f);
    __syncthreads();

    fft8192(bufA, bufB, twS, tid);           // K spectrum -> bufB
    for (int i = tid; i < 8192; i += 512) bufK[i] = bufB[i];
    __syncthreads();

    float bd = bias[d];
#pragma unroll
    for (int pr = 0; pr < 2; pr++) {
        const float* x0 = x + ((size_t)(2 * pr) * DMODEL + d) * LSEQ;
        const float* x1 = x + ((size_t)(2 * pr + 1) * DMODEL + d) * LSEQ;

        // pack two real signals as one complex signal, zero-padded to 8192
        for (int i = tid; i < 4096; i += 512) bufA[i] = make_float2(x0[i], x1[i]);
        for (int i = tid; i < 4096; i += 512) bufA[4096 + i] = make_float2(0.0f, 0.0f);
        __syncthreads();

        fft8192(bufA, bufB, twS, tid);       // W = U0 + i*U1 -> bufB

        // Z = W * K; store conj(Z) for inverse-via-forward
        for (int i = tid; i < 8192; i += 512) {
            float2 z = cmul(bufB[i], bufK[i]);
            bufA[i] = make_float2(z.x, -z.y);
        }
        __syncthreads();

        fft8192(bufA, bufB, twS, tid);       // fft(conj Z); ifft = conj(.)/N

        float* o0 = out + ((size_t)(2 * pr) * DMODEL + d) * LSEQ;
        float* o1 = out + ((size_t)(2 * pr + 1) * DMODEL + d) * LSEQ;
        const float inv = 1.0f / 8192.0f;
        for (int i = tid; i < 4096; i += 512) {
            float2 y = bufB[i];                       // conj/N: re = y.x/N, im = -y.y/N
            o0[i] =  y.x * inv + x0[i] * bd;
            o1[i] = -y.y * inv + x1[i] * bd;
        }
        __syncthreads();
    }
}

// =====================================================================
extern "C" void kernel_launch(void* const* d_in, const int* in_sizes, int n_in,
                              void* d_out, int out_size)
{
    (void)n_in; (void)out_size;
    const float* x = (const float*)d_in[0];
    // 'L' may or may not appear as a scalar input after x; detect by size.
    int base = (in_sizes[1] == 1) ? 2 : 1;
    const float* z      = (const float*)d_in[base + 0];
    // t = d_in[base+1] (unused; t[l] = l/4095 computed arithmetically)
    const float* deltas = (const float*)d_in[base + 2];
    const float* W1     = (const float*)d_in[base + 3];
    const float* b1     = (const float*)d_in[base + 4];
    const float* freq   = (const float*)d_in[base + 5];
    const float* W2     = (const float*)d_in[base + 6];
    const float* b2     = (const float*)d_in[base + 7];
    const float* W3     = (const float*)d_in[base + 8];
    const float* b3     = (const float*)d_in[base + 9];
    const float* W4     = (const float*)d_in[base + 10];
    const float* bias   = (const float*)d_in[base + 11];
    float* out = (float*)d_out;

    k_filter_mlp<<<1024, 256>>>(z, deltas, W1, b1, freq, W2, b2, W3, b3);

    dim3 g2(64, 16);
    k_filter_gemm<<<g2, 256>>>(W4);

    const int smem_bytes = 26624 * (int)sizeof(float2);   // 208 KB
    cudaFuncSetAttribute(k_conv, cudaFuncAttributeMaxDynamicSharedMemorySize, smem_bytes);
    k_conv<<<DMODEL, 512, smem_bytes>>>(x, bias, out);
}

// round 4
// speedup vs baseline: 1.5488x; 1.5488x over previous
#include <cuda_runtime.h>
#include <math.h>

#define LSEQ   4096
#define NFFT   8192
#define DMODEL 1024
#define ORDER  64
#define EMB    5

// ---- scratch (static device globals: allowed) ----
__device__ float  g_h3[LSEQ * ORDER];
__device__ float  g_k [DMODEL * LSEQ];
__device__ float  g_decayA[DMODEL * 64];
__device__ float  g_decayB[DMODEL * 64];
__device__ float2 g_tw[2048];                // quarter twiddle table of W8192

// =====================================================================
// Kernel 1: implicit-filter MLP -> h3[l][o], plus decay + twiddle tables
// grid 128, block 256 (4 rows x 64 features, 8 row-groups per block)
// =====================================================================
#define MLP_BLOCKS 128
__global__ __launch_bounds__(256) void k_filter_mlp(
    const float* __restrict__ z, const float* __restrict__ deltas,
    const float* __restrict__ W1, const float* __restrict__ b1,
    const float* __restrict__ freq, const float* __restrict__ W2,
    const float* __restrict__ b2, const float* __restrict__ W3,
    const float* __restrict__ b3)
{
    __shared__ float sW1[ORDER * EMB], sb1[ORDER], sb2[ORDER], sb3[ORDER], sfreq[ORDER];
    __shared__ float sW2T[ORDER][ORDER + 1];   // transposed: [j][o], padded
    __shared__ float sW3T[ORDER][ORDER + 1];
    __shared__ float h1[4][ORDER], h2[4][ORDER];

    int tid = threadIdx.x;
    for (int i = tid; i < ORDER * EMB; i += 256) sW1[i] = W1[i];
    for (int i = tid; i < ORDER * ORDER; i += 256) {
        int o = i >> 6, j = i & 63;
        sW2T[j][o] = W2[i];                    // stride-65 writes: conflict-free
        sW3T[j][o] = W3[i];
    }
    if (tid < ORDER) { sb1[tid] = b1[tid]; sb2[tid] = b2[tid]; sb3[tid] = b3[tid]; sfreq[tid] = freq[tid]; }
    __syncthreads();

    int r = tid >> 6;       // 0..3
    int o = tid & 63;       // 0..63

    for (int rg = 0; rg < 8; rg++) {
        int l = blockIdx.x * 32 + rg * 4 + r;

        float acc = sb1[o];
        const float* zl = z + l * EMB;
#pragma unroll
        for (int e = 0; e < EMB; e++) acc += zl[e] * sW1[o * EMB + e];
        h1[r][o] = __sinf(sfreq[o] * acc);
        __syncthreads();

        acc = sb2[o];
#pragma unroll 16
        for (int j = 0; j < ORDER; j++) acc += h1[r][j] * sW2T[j][o];  // broadcast + contiguous
        h2[r][o] = __sinf(sfreq[o] * acc);
        __syncthreads();

        acc = sb3[o];
#pragma unroll 16
        for (int j = 0; j < ORDER; j++) acc += h2[r][j] * sW3T[j][o];
        g_h3[l * ORDER + o] = __sinf(sfreq[o] * acc);
        __syncthreads();
    }

    // decay factorization: decay(d,l) = A[d][l>>6] * B[d][l&63]
    for (int g = blockIdx.x * 256 + tid; g < DMODEL * 64; g += MLP_BLOCKS * 256) {
        int d = g >> 6, i = g & 63;
        float a = fabsf(deltas[d]);
        g_decayA[g] = __expf(-a * (64.0f * (float)i) * (1.0f / 4095.0f));
        g_decayB[g] = __expf(-a * (float)i * (1.0f / 4095.0f));
    }
    // quarter twiddle table: w[j] = exp(-2*pi*i*j/8192)
    for (int g = blockIdx.x * 256 + tid; g < 2048; g += MLP_BLOCKS * 256) {
        float ang = -2.0f * 3.14159265358979323846f * (float)g * (1.0f / 8192.0f);
        float s, c;
        sincosf(ang, &s, &c);
        g_tw[g] = make_float2(c, s);
    }
}

// =====================================================================
// Kernel 2: k[d][l] = (h3[l][:] . W4[d][:]) * decay(d,l)
// =====================================================================
__global__ __launch_bounds__(256) void k_filter_gemm(const float* __restrict__ W4)
{
    __shared__ float sh[64][65];
    __shared__ float sw[64][65];
    int lt = blockIdx.x, dt = blockIdx.y;
    int tid = threadIdx.x;

    for (int i = tid; i < 64 * 64; i += 256) {
        int row = i >> 6, col = i & 63;
        sh[row][col] = g_h3[(lt * 64 + row) * 64 + col];
        sw[row][col] = W4[(dt * 64 + row) * 64 + col];
    }
    __syncthreads();

    int tx = tid & 15, ty = tid >> 4;
    float acc[4][4];
#pragma unroll
    for (int r = 0; r < 4; r++)
#pragma unroll
        for (int c = 0; c < 4; c++) acc[r][c] = 0.0f;

#pragma unroll 8
    for (int o = 0; o < 64; o++) {
        float a[4], b[4];
#pragma unroll
        for (int r = 0; r < 4; r++) a[r] = sh[tx + 16 * r][o];
#pragma unroll
        for (int c = 0; c < 4; c++) b[c] = sw[ty + 16 * c][o];
#pragma unroll
        for (int r = 0; r < 4; r++)
#pragma unroll
            for (int c = 0; c < 4; c++) acc[r][c] += a[r] * b[c];
    }

#pragma unroll
    for (int c = 0; c < 4; c++) {
        int d = dt * 64 + ty + 16 * c;
        float dA = g_decayA[d * 64 + lt];
#pragma unroll
        for (int r = 0; r < 4; r++) {
            int li = tx + 16 * r;
            g_k[(size_t)d * LSEQ + lt * 64 + li] = acc[r][c] * dA * g_decayB[d * 64 + li];
        }
    }
}

// =====================================================================
// Kernel 3: per-channel FFT convolution
// 8192 = 2 * 16 * 16 * 16; radix-2 fused into load; 3 radix-16 smem rounds.
// All smem buffers use padded addressing phi(a) = a + (a>>4) (conflict-free).
// =====================================================================
#define PHI(a) ((a) + ((a) >> 4))
#define BUFSZ 8704

__device__ __forceinline__ float2 cmul(float2 a, float2 b) {
    return make_float2(a.x * b.x - a.y * b.y, a.x * b.y + a.y * b.x);
}
__device__ __forceinline__ float2 cmulc(float2 a, float cr, float ci) {
    return make_float2(a.x * cr - a.y * ci, a.x * ci + a.y * cr);
}
__device__ __forceinline__ float2 cadd(float2 a, float2 b) { return make_float2(a.x + b.x, a.y + b.y); }
__device__ __forceinline__ float2 csub(float2 a, float2 b) { return make_float2(a.x - b.x, a.y - b.y); }
__device__ __forceinline__ float2 cmulnegi(float2 a) { return make_float2(a.y, -a.x); }   // a * (-i)

// W8192^e for e in [0, 8192): quarter table + quadrant rotation
__device__ __forceinline__ float2 twget(const float2* __restrict__ tw, int e) {
    float2 c = tw[e & 2047];
    int k = (e >> 11) & 3;
    if (k == 1)      c = make_float2(c.y, -c.x);    // * (-i)
    else if (k == 2) c = make_float2(-c.x, -c.y);   // * (-1)
    else if (k == 3) c = make_float2(-c.y, c.x);    // * (+i)
    return c;
}

// radix-4 DIF butterfly (no twiddles), in place
__device__ __forceinline__ void bf4(float2& x0, float2& x1, float2& x2, float2& x3) {
    float2 t0 = cadd(x0, x2), t1 = csub(x0, x2);
    float2 t2 = cadd(x1, x3), t3 = csub(x1, x3);
    float2 it3 = cmulnegi(t3);
    x0 = cadd(t0, t2); x2 = csub(t0, t2);
    x1 = cadd(t1, it3); x3 = csub(t1, it3);
}

#define C16 0.9238795325112867f
#define S16 0.3826834323650898f
#define R2H 0.7071067811865476f

// Stockham radix-16 stage: stride s = 1<<SLOG. 512 threads, 1 butterfly each.
template <int SLOG, bool TW>
__device__ __forceinline__ void r16stage(const float2* __restrict__ src, float2* __restrict__ dst,
                                         const float2* __restrict__ tws, int tid)
{
    int q = tid & ((1 << SLOG) - 1);
    int p = tid >> SLOG;
    int sp = p << SLOG;

    float2 a[16];
    int lb = tid + (tid >> 4);          // PHI(tid); PHI(tid + 512j) = lb + 544j
#pragma unroll
    for (int j = 0; j < 16; j++) a[j] = src[lb + 544 * j];

    // step 1: 4 radix-4 DFTs over j2 (slots a[j1 + 4m] hold c[j1][m])
    bf4(a[0], a[4], a[8],  a[12]);
    bf4(a[1], a[5], a[9],  a[13]);
    bf4(a[2], a[6], a[10], a[14]);
    bf4(a[3], a[7], a[11], a[15]);

    // step 2: internal twiddles W16^{j1*m}
    a[5]  = cmulc(a[5],  C16, -S16);   // W16^1
    a[9]  = cmulc(a[9],  R2H, -R2H);   // W16^2
    a[13] = cmulc(a[13], S16, -C16);   // W16^3
    a[6]  = cmulc(a[6],  R2H, -R2H);   // W16^2
    a[10] = cmulnegi(a[10]);           // W16^4
    a[14] = cmulc(a[14], -R2H, -R2H);  // W16^6
    a[7]  = cmulc(a[7],  S16, -C16);   // W16^3
    a[11] = cmulc(a[11], -R2H, -R2H);  // W16^6
    a[15] = cmulc(a[15], -C16,  S16);  // W16^9

    // step 3: 4 radix-4 DFTs over j1 (B[m+4k2] lands in slot a[k2+4m])
    bf4(a[0],  a[1],  a[2],  a[3]);
    bf4(a[4],  a[5],  a[6],  a[7]);
    bf4(a[8],  a[9],  a[10], a[11]);
    bf4(a[12], a[13], a[14], a[15]);

    int ob = q + (p << (SLOG + 4));
#pragma unroll
    for (int r = 0; r < 16; r++) {
        int slot = ((r & 3) << 2) | (r >> 2);
        float2 v = a[slot];
        if (TW && r > 0) v = cmul(v, twget(tws, r * sp));
        int addr = ob + (r << SLOG);
        dst[addr + (addr >> 4)] = v;
    }
}

// 3 radix-16 rounds: A (r2-stage output) -> ... -> result in B
__device__ __forceinline__ void fft_rounds(float2* A, float2* B, const float2* tws, int tid)
{
    r16stage<1, true >(A, B, tws, tid); __syncthreads();   // s=2
    r16stage<5, true >(B, A, tws, tid); __syncthreads();   // s=32
    r16stage<9, false>(A, B, tws, tid); __syncthreads();   // s=512, p=0 -> no twiddles
}

__global__ __launch_bounds__(512, 1) void k_conv(const float* __restrict__ x,
                                                 const float* __restrict__ bias,
                                                 float* __restrict__ out)
{
    extern __shared__ float2 sm[];
    float2* A   = sm;
    float2* Bb  = sm + BUFSZ;
    float2* Kb  = sm + 2 * BUFSZ;
    float2* tws = sm + 3 * BUFSZ;    // 2048 entries

    int tid = threadIdx.x;
    int d = blockIdx.x;

    for (int i = tid; i < 2048; i += 512) tws[i] = g_tw[i];
    __syncthreads();

    // ---- K spectrum: fused radix-2 (zero-padded) + 3 rounds ----
    const float* kg = g_k + (size_t)d * LSEQ;
#pragma unroll
    for (int it = 0; it < 8; it++) {
        int p = tid + it * 512;                 // [0,4096)
        float2 v = make_float2(kg[p], 0.0f);
        float2 w = twget(tws, p);
        int o = PHI(2 * p);
        A[o]     = v;                           // x + 0
        A[o + 1] = cmul(v, w);                  // (x - 0) * w^p
    }
    __syncthreads();
    fft_rounds(A, Bb, tws, tid);
    for (int i = tid; i < BUFSZ; i += 512) Kb[i] = Bb[i];
    __syncthreads();

    float bd = bias[d];
    const float inv = 1.0f / 8192.0f;

#pragma unroll
    for (int pr = 0; pr < 2; pr++) {
        const float* x0 = x + ((size_t)(2 * pr) * DMODEL + d) * LSEQ;
        const float* x1 = x + ((size_t)(2 * pr + 1) * DMODEL + d) * LSEQ;

        // forward FFT of packed x0 + i*x1: fused radix-2 from global
#pragma unroll
        for (int it = 0; it < 8; it++) {
            int p = tid + it * 512;
            float2 v = make_float2(x0[p], x1[p]);
            float2 w = twget(tws, p);
            int o = PHI(2 * p);
            A[o]     = v;
            A[o + 1] = cmul(v, w);
        }
        __syncthreads();
        fft_rounds(A, Bb, tws, tid);            // W spectrum in Bb

        // inverse via forward-of-conjugate: fuse product + conj + radix-2
#pragma unroll
        for (int it = 0; it < 8; it++) {
            int idx = tid + it * 512;           // [0,4096)
            int i0 = PHI(idx), i1 = PHI(idx + 4096);
            float2 zl = cmul(Bb[i0], Kb[i0]); zl.y = -zl.y;
            float2 zh = cmul(Bb[i1], Kb[i1]); zh.y = -zh.y;
            float2 s = cadd(zl, zh);
            float2 dif = csub(zl, zh);
            float2 w = twget(tws, idx);
            int o = PHI(2 * idx);
            A[o]     = s;
            A[o + 1] = cmul(dif, w);
        }
        __syncthreads();
        fft_rounds(A, Bb, tws, tid);            // fft(conj Z) in Bb

        float* o0 = out + ((size_t)(2 * pr) * DMODEL + d) * LSEQ;
        float* o1 = out + ((size_t)(2 * pr + 1) * DMODEL + d) * LSEQ;
#pragma unroll
        for (int it = 0; it < 8; it++) {
            int i = tid + it * 512;
            float2 y = Bb[PHI(i)];              // ifft = conj(.)/N
            o0[i] =  y.x * inv + x0[i] * bd;
            o1[i] = -y.y * inv + x1[i] * bd;
        }
        __syncthreads();
    }
}

// =====================================================================
extern "C" void kernel_launch(void* const* d_in, const int* in_sizes, int n_in,
                              void* d_out, int out_size)
{
    (void)n_in; (void)out_size;
    const float* x = (const float*)d_in[0];
    int base = (in_sizes[1] == 1) ? 2 : 1;
    const float* z      = (const float*)d_in[base + 0];
    const float* deltas = (const float*)d_in[base + 2];
    const float* W1     = (const float*)d_in[base + 3];
    const float* b1     = (const float*)d_in[base + 4];
    const float* freq   = (const float*)d_in[base + 5];
    const float* W2     = (const float*)d_in[base + 6];
    const float* b2     = (const float*)d_in[base + 7];
    const float* W3     = (const float*)d_in[base + 8];
    const float* b3     = (const float*)d_in[base + 9];
    const float* W4     = (const float*)d_in[base + 10];
    const float* bias   = (const float*)d_in[base + 11];
    float* out = (float*)d_out;

    k_filter_mlp<<<MLP_BLOCKS, 256>>>(z, deltas, W1, b1, freq, W2, b2, W3, b3);

    dim3 g2(64, 16);
    k_filter_gemm<<<g2, 256>>>(W4);

    const int smem_bytes = (3 * BUFSZ + 2048) * (int)sizeof(float2);   // 225,280 B
    cudaFuncSetAttribute(k_conv, cudaFuncAttributeMaxDynamicSharedMemorySize, smem_bytes);
    k_conv<<<DMODEL, 512, smem_bytes>>>(x, bias, out);
}